// round 15
// baseline (speedup 1.0000x reference)
#include <cuda_runtime.h>
#include <math.h>
#include <stdint.h>

// ============================================================================
// Problem constants
//   x_l:  [N, 64, 2l+1]   l = 0,1,2
//   W1_l, W2_l: [64, 16]
//   W3_l: [tp_mult_l, 64]  tp_mult = {768, 1536, 1536}
//   out:  [N, 576]  (64*1 | 64*3 | 64*5)
//
// NOTE input order (reference setup_inputs dict insertion order):
//   0:x0 1:x1 2:x2 | 3:W1_0 4:W2_0 5:W1_1 6:W2_1 7:W1_2 8:W2_2 | 9:W3_0 10:W3_1 11:W3_2
// ============================================================================

#define MAX_N 20000

// Scratch: branch-linear outputs a,b per row: 144 floats each
// layout per row: l=0: [0..16) v ; l=1: [16..64) v*3+i ; l=2: [64..144) v*5+i
__device__ float g_A[MAX_N * 144];
__device__ float g_B[MAX_N * 144];

// Sparse CG tables per (path, k): entries (i<<3|j, coeff)
__device__ int   g_cgcnt[15][5];
__device__ int   g_cgij [15][5][32];
__device__ float g_cgval[15][5][32];

// PATHS in reference enumeration order
__constant__ int c_pl1[15] = {0,0,0,1,1,1,1,1,1,2,2,2,2,2,2};
__constant__ int c_pl2[15] = {0,1,2,0,1,1,1,2,2,0,1,1,2,2,2};
__constant__ int c_pl3[15] = {0,1,2,1,0,1,2,1,2,2,1,2,0,1,2};
__constant__ int c_aoff[3] = {0,16,64};
// per-output-l path lists (global path indices, in PATHS order)
__constant__ int c_lp[3][6] = {{0,4,12,0,0,0},{1,3,5,7,10,13},{2,6,8,9,11,14}};

// ============================================================================
// Kernel 0: compute real-basis CG coefficients on device (double precision),
// exactly mirroring the reference's _cg_complex / _q / _real_cg.
// ============================================================================

__device__ __forceinline__ double dfact(int n) {
    double r = 1.0;
    for (int i = 2; i <= n; ++i) r *= (double)i;
    return r;
}

__device__ double cgc(int j1, int m1, int j2, int m2, int j3, int m3) {
    if (m1 + m2 != m3) return 0.0;
    double pre = sqrt((2.0 * j3 + 1.0) * dfact(j1 + j2 - j3) * dfact(j1 - j2 + j3) *
                      dfact(-j1 + j2 + j3) / dfact(j1 + j2 + j3 + 1));
    pre *= sqrt(dfact(j1 + m1) * dfact(j1 - m1) * dfact(j2 + m2) * dfact(j2 - m2) *
                dfact(j3 + m3) * dfact(j3 - m3));
    int kmin = max(0, max(j2 - j3 - m1, j1 - j3 + m2));
    int kmax = min(j1 + j2 - j3, min(j1 - m1, j2 + m2));
    double s = 0.0;
    for (int k = kmin; k <= kmax; ++k) {
        double term = 1.0 / (dfact(k) * dfact(j1 + j2 - j3 - k) * dfact(j1 - m1 - k) *
                             dfact(j2 + m2 - k) * dfact(j3 - j2 + m1 + k) * dfact(j3 - j1 - m2 + k));
        s += (k & 1) ? -term : term;
    }
    return pre * s;
}

// Q: complex->real change of basis. row = real index (l+m_real), col = complex (l+m)
__device__ void buildQ(int l, double* Qre, double* Qim) {
    int d = 2 * l + 1;
    for (int t = 0; t < d * d; ++t) { Qre[t] = 0.0; Qim[t] = 0.0; }
    Qre[l * d + l] = 1.0;
    double r2i = 1.0 / sqrt(2.0);
    for (int m = 1; m <= l; ++m) {
        double sgn = (m & 1) ? -1.0 : 1.0;
        Qre[(l + m) * d + (l + m)] = sgn * r2i;
        Qre[(l + m) * d + (l - m)] = r2i;
        Qim[(l - m) * d + (l - m)] = r2i;
        Qim[(l - m) * d + (l + m)] = -sgn * r2i;
    }
}

__global__ void cg_init_kernel() {
    int p = threadIdx.x;
    if (p >= 15) return;
    int l1 = c_pl1[p], l2 = c_pl2[p], l3 = c_pl3[p];
    int d1 = 2 * l1 + 1, d2 = 2 * l2 + 1, d3 = 2 * l3 + 1;

    double Q1r[25], Q1i[25], Q2r[25], Q2i[25], Q3r[25], Q3i[25];
    buildQ(l1, Q1r, Q1i); buildQ(l2, Q2r, Q2i); buildQ(l3, Q3r, Q3i);

    double Mr[5][5][5], Mi[5][5][5];
    double maxr = 0.0, maxi = 0.0;
    for (int i = 0; i < d1; ++i)
    for (int j = 0; j < d2; ++j)
    for (int k = 0; k < d3; ++k) {
        double sr = 0.0, si = 0.0;
        for (int a = 0; a < d1; ++a) {
            double q1r = Q1r[i * d1 + a], q1i = -Q1i[i * d1 + a];  // conj
            if (q1r == 0.0 && q1i == 0.0) continue;
            for (int b = 0; b < d2; ++b) {
                double q2r = Q2r[j * d2 + b], q2i = -Q2i[j * d2 + b];  // conj
                if (q2r == 0.0 && q2i == 0.0) continue;
                int m1 = a - l1, m2 = b - l2, m3 = m1 + m2;
                if (m3 < -l3 || m3 > l3) continue;
                double C = cgc(l1, m1, l2, m2, l3, m3);
                if (C == 0.0) continue;
                int c = m3 + l3;
                double q3r = Q3r[k * d3 + c], q3i = Q3i[k * d3 + c];
                double q12r = q1r * q2r - q1i * q2i;
                double q12i = q1r * q2i + q1i * q2r;
                sr += (q12r * q3r - q12i * q3i) * C;
                si += (q12r * q3i + q12i * q3r) * C;
            }
        }
        Mr[i][j][k] = sr; Mi[i][j][k] = si;
        maxr = fmax(maxr, fabs(sr));
        maxi = fmax(maxi, fabs(si));
    }
    bool flip = (maxi > maxr);   // reference multiplies by -1j; real part becomes Mi
    for (int k = 0; k < d3; ++k) {
        int cnt = 0;
        for (int i = 0; i < d1; ++i)
        for (int j = 0; j < d2; ++j) {
            double val = flip ? Mi[i][j][k] : Mr[i][j][k];
            if (fabs(val) > 1e-8) {
                g_cgij[p][k][cnt] = (i << 3) | j;
                g_cgval[p][k][cnt] = (float)val;
                ++cnt;
            }
        }
        g_cgcnt[p][k] = cnt;
    }
    // zero unused k slots
    for (int k = d3; k < 5; ++k) g_cgcnt[p][k] = 0;
}

// ============================================================================
// Kernel 1: branch linears  a = (x @ W1)/8,  b = (x @ W2)/8  -> g_A, g_B
// one warp per row n
// ============================================================================

__global__ __launch_bounds__(256) void ab_kernel(
    const float* __restrict__ x0, const float* __restrict__ x1, const float* __restrict__ x2,
    const float* __restrict__ W10, const float* __restrict__ W11, const float* __restrict__ W12,
    const float* __restrict__ W20, const float* __restrict__ W21, const float* __restrict__ W22,
    int Nrows)
{
    __shared__ float sx[8][576];
    const int lane = threadIdx.x & 31;
    const int wid = threadIdx.x >> 5;
    const int n = blockIdx.x * 8 + wid;
    if (n >= Nrows) return;

    for (int t = lane; t < 64;  t += 32) sx[wid][t]       = x0[(size_t)n * 64  + t];
    for (int t = lane; t < 192; t += 32) sx[wid][64 + t]  = x1[(size_t)n * 192 + t];
    for (int t = lane; t < 320; t += 32) sx[wid][256 + t] = x2[(size_t)n * 320 + t];
    __syncwarp();

    const float* W1s[3] = {W10, W11, W12};
    const float* W2s[3] = {W20, W21, W22};

    #pragma unroll 1
    for (int o = lane; o < 288; o += 32) {
        const int branch = (o >= 144);
        const int ol = o - branch * 144;
        int l, v, i, xo, d;
        if (ol < 16)      { l = 0; v = ol;            i = 0;          xo = 0;   d = 1; }
        else if (ol < 64) { l = 1; int t = ol - 16;   v = t / 3; i = t - 3 * v; xo = 64;  d = 3; }
        else              { l = 2; int t = ol - 64;   v = t / 5; i = t - 5 * v; xo = 256; d = 5; }
        const float* W = branch ? W2s[l] : W1s[l];
        float acc = 0.f;
        #pragma unroll 8
        for (int u = 0; u < 64; ++u)
            acc = fmaf(sx[wid][xo + u * d + i], W[u * 16 + v], acc);
        (branch ? g_B : g_A)[(size_t)n * 144 + ol] = acc * 0.125f;
    }
}

// ============================================================================
// Kernel 2 (x3): fused CG tensor product + W3 GEMM for one output degree LOUT.
//   CTA: 256 threads, M=32 rows. smem: A,B rows + z-chunk [NK][32][64].
//   GEMM: warp wid owns rows wid*4..+3; thread owns w = {lane, lane+32};
//   accumulators acc[4 rows][2 w][NK].
// ============================================================================

template<int LOUT, int NP>
__global__ __launch_bounds__(256, 2) void tp_kernel(
    const float* __restrict__ W3, float* __restrict__ out, int Nrows)
{
    constexpr int NK = 2 * LOUT + 1;
    constexpr int M = 32;
    constexpr int OOFF = (LOUT == 0) ? 0 : ((LOUT == 1) ? 64 : 256);

    extern __shared__ float sm[];
    float* sA = sm;                 // [M][144]
    float* sB = sm + M * 144;       // [M][144]
    float* sZ = sm + 2 * M * 144;   // [NK][M][64]

    const int tid  = threadIdx.x;
    const int lane = tid & 31;
    const int wid  = tid >> 5;
    const int n0   = blockIdx.x * M;

    // ---- load A,B rows ----
    for (int idx = tid; idx < M * 144; idx += 256) {
        const int r = idx / 144;
        const int c = idx - r * 144;
        if (n0 + r < Nrows) {
            sA[idx] = g_A[(size_t)(n0 + r) * 144 + c];
            sB[idx] = g_B[(size_t)(n0 + r) * 144 + c];
        } else {
            sA[idx] = 0.f; sB[idx] = 0.f;
        }
    }

    float acc[4][2][NK];
    #pragma unroll
    for (int r = 0; r < 4; ++r)
        #pragma unroll
        for (int h = 0; h < 2; ++h)
            #pragma unroll
            for (int k = 0; k < NK; ++k) acc[r][h][k] = 0.f;

    const int uvc = tid & 63;       // uv within chunk
    const int rb  = tid >> 6;       // 0..3 (z-compute row base)
    const int v   = uvc & 15;
    int rbase[8];
    #pragma unroll
    for (int s = 0; s < 8; ++s) rbase[s] = (rb + 4 * s) * 144;
    const int warp_r0 = wid * 4;    // GEMM rows for this warp

    __syncthreads();

    #pragma unroll 1
    for (int p = 0; p < NP; ++p) {
        const int pg   = c_lp[LOUT][p];
        const int l1   = c_pl1[pg], l2 = c_pl2[pg];
        const int aoff = c_aoff[l1], boff = c_aoff[l2];
        const int d1   = 2 * l1 + 1, d2 = 2 * l2 + 1;
        const float* bp0 = sB + boff + v * d2;

        #pragma unroll 1
        for (int ch = 0; ch < 4; ++ch) {
            // ---- z-compute: this thread handles (rows rb+4s, uv = ch*64+uvc) ----
            {
                const int u = ch * 4 + (uvc >> 4);
                const float* ap0 = sA + aoff + u * d1;
                #pragma unroll
                for (int k = 0; k < NK; ++k) {
                    float zk[8];
                    #pragma unroll
                    for (int s = 0; s < 8; ++s) zk[s] = 0.f;
                    const int cnt = g_cgcnt[pg][k];
                    for (int e = 0; e < cnt; ++e) {
                        const int   ij = g_cgij[pg][k][e];
                        const float c  = g_cgval[pg][k][e];
                        const int i = ij >> 3, j = ij & 7;
                        #pragma unroll
                        for (int s = 0; s < 8; ++s)
                            zk[s] = fmaf(ap0[rbase[s] + i] * bp0[rbase[s] + j], c, zk[s]);
                    }
                    #pragma unroll
                    for (int s = 0; s < 8; ++s)
                        sZ[k * (M * 64) + (rb + 4 * s) * 64 + uvc] = zk[s];
                }
            }
            __syncthreads();

            // ---- GEMM over this 64-wide K chunk ----
            const float* W3c = W3 + (size_t)(p * 256 + ch * 64) * 64;
            #pragma unroll 2
            for (int q = 0; q < 64; ++q) {
                const float w0 = W3c[q * 64 + lane];
                const float w1 = W3c[q * 64 + lane + 32];
                #pragma unroll
                for (int r = 0; r < 4; ++r) {
                    const int zb = (warp_r0 + r) * 64 + q;
                    #pragma unroll
                    for (int k = 0; k < NK; ++k) {
                        const float zv = sZ[k * (M * 64) + zb];
                        acc[r][0][k] = fmaf(w0, zv, acc[r][0][k]);
                        acc[r][1][k] = fmaf(w1, zv, acc[r][1][k]);
                    }
                }
            }
            __syncthreads();
        }
    }

    // ---- epilogue: y = acc / sqrt(tp_mult) ----
    const float scale = rsqrtf((float)(NP * 256));
    #pragma unroll
    for (int r = 0; r < 4; ++r) {
        const int n = n0 + warp_r0 + r;
        if (n >= Nrows) continue;
        float* o = out + (size_t)n * 576 + OOFF;
        #pragma unroll
        for (int k = 0; k < NK; ++k) {
            o[lane * NK + k]        = acc[r][0][k] * scale;
            o[(lane + 32) * NK + k] = acc[r][1][k] * scale;
        }
    }
}

// ============================================================================
// kernel_launch
// Input order follows the reference setup_inputs() dict insertion order:
//   x0,x1,x2, W1_0,W2_0, W1_1,W2_1, W1_2,W2_2, W3_0,W3_1,W3_2
// (W1/W2 are INTERLEAVED per degree — they are created in the same loop.)
// ============================================================================

extern "C" void kernel_launch(void* const* d_in, const int* in_sizes, int n_in,
                              void* d_out, int out_size)
{
    const float* x0  = (const float*)d_in[0];
    const float* x1  = (const float*)d_in[1];
    const float* x2  = (const float*)d_in[2];
    const float* W10 = (const float*)d_in[3];   // W1_0
    const float* W20 = (const float*)d_in[4];   // W2_0
    const float* W11 = (const float*)d_in[5];   // W1_1
    const float* W21 = (const float*)d_in[6];   // W2_1
    const float* W12 = (const float*)d_in[7];   // W1_2
    const float* W22 = (const float*)d_in[8];   // W2_2
    const float* W30 = (const float*)d_in[9];
    const float* W31 = (const float*)d_in[10];
    const float* W32 = (const float*)d_in[11];
    float* out = (float*)d_out;

    const int N = in_sizes[0] / 64;   // x0 is [N,64,1]

    const int smem0 = (2 * 32 * 144 + 1 * 32 * 64) * 4;  // 45056
    const int smem1 = (2 * 32 * 144 + 3 * 32 * 64) * 4;  // 61440
    const int smem2 = (2 * 32 * 144 + 5 * 32 * 64) * 4;  // 77824
    cudaFuncSetAttribute(tp_kernel<0, 3>, cudaFuncAttributeMaxDynamicSharedMemorySize, smem0);
    cudaFuncSetAttribute(tp_kernel<1, 6>, cudaFuncAttributeMaxDynamicSharedMemorySize, smem1);
    cudaFuncSetAttribute(tp_kernel<2, 6>, cudaFuncAttributeMaxDynamicSharedMemorySize, smem2);

    cg_init_kernel<<<1, 32>>>();
    ab_kernel<<<(N + 7) / 8, 256>>>(x0, x1, x2, W10, W11, W12, W20, W21, W22, N);

    const int nb = (N + 31) / 32;
    tp_kernel<0, 3><<<nb, 256, smem0>>>(W30, out, N);
    tp_kernel<1, 6><<<nb, 256, smem1>>>(W31, out, N);
    tp_kernel<2, 6><<<nb, 256, smem2>>>(W32, out, N);
}

// round 16
// speedup vs baseline: 1.0033x; 1.0033x over previous
#include <cuda_runtime.h>
#include <math.h>
#include <stdint.h>

// ============================================================================
// Problem constants
//   x_l:  [N, 64, 2l+1]   l = 0,1,2
//   W1_l, W2_l: [64, 16]
//   W3_l: [tp_mult_l, 64]  tp_mult = {768, 1536, 1536}
//   out:  [N, 576]  (64*1 | 64*3 | 64*5)
//
// NOTE input order (reference setup_inputs dict insertion order):
//   0:x0 1:x1 2:x2 | 3:W1_0 4:W2_0 5:W1_1 6:W2_1 7:W1_2 8:W2_2 | 9:W3_0 10:W3_1 11:W3_2
// ============================================================================

#define MAX_N 20000

// Scratch: branch-linear outputs a,b per row: 144 floats each
// layout per row: l=0: [0..16) v ; l=1: [16..64) v*3+i ; l=2: [64..144) v*5+i
__device__ float g_A[MAX_N * 144];
__device__ float g_B[MAX_N * 144];

// Sparse CG tables per (path, k): entries (i<<3|j, coeff)
__device__ int   g_cgcnt[15][5];
__device__ int   g_cgij [15][5][32];
__device__ float g_cgval[15][5][32];

// PATHS in reference enumeration order
__constant__ int c_pl1[15] = {0,0,0,1,1,1,1,1,1,2,2,2,2,2,2};
__constant__ int c_pl2[15] = {0,1,2,0,1,1,1,2,2,0,1,1,2,2,2};
__constant__ int c_pl3[15] = {0,1,2,1,0,1,2,1,2,2,1,2,0,1,2};
__constant__ int c_aoff[3] = {0,16,64};
// per-output-l path lists (global path indices, in PATHS order)
__constant__ int c_lp[3][6] = {{0,4,12,0,0,0},{1,3,5,7,10,13},{2,6,8,9,11,14}};

// ============================================================================
// Kernel 0: compute real-basis CG coefficients on device (double precision),
// exactly mirroring the reference's _cg_complex / _q / _real_cg.
// ============================================================================

__device__ __forceinline__ double dfact(int n) {
    double r = 1.0;
    for (int i = 2; i <= n; ++i) r *= (double)i;
    return r;
}

__device__ double cgc(int j1, int m1, int j2, int m2, int j3, int m3) {
    if (m1 + m2 != m3) return 0.0;
    double pre = sqrt((2.0 * j3 + 1.0) * dfact(j1 + j2 - j3) * dfact(j1 - j2 + j3) *
                      dfact(-j1 + j2 + j3) / dfact(j1 + j2 + j3 + 1));
    pre *= sqrt(dfact(j1 + m1) * dfact(j1 - m1) * dfact(j2 + m2) * dfact(j2 - m2) *
                dfact(j3 + m3) * dfact(j3 - m3));
    int kmin = max(0, max(j2 - j3 - m1, j1 - j3 + m2));
    int kmax = min(j1 + j2 - j3, min(j1 - m1, j2 + m2));
    double s = 0.0;
    for (int k = kmin; k <= kmax; ++k) {
        double term = 1.0 / (dfact(k) * dfact(j1 + j2 - j3 - k) * dfact(j1 - m1 - k) *
                             dfact(j2 + m2 - k) * dfact(j3 - j2 + m1 + k) * dfact(j3 - j1 - m2 + k));
        s += (k & 1) ? -term : term;
    }
    return pre * s;
}

// Q: complex->real change of basis. row = real index (l+m_real), col = complex (l+m)
__device__ void buildQ(int l, double* Qre, double* Qim) {
    int d = 2 * l + 1;
    for (int t = 0; t < d * d; ++t) { Qre[t] = 0.0; Qim[t] = 0.0; }
    Qre[l * d + l] = 1.0;
    double r2i = 1.0 / sqrt(2.0);
    for (int m = 1; m <= l; ++m) {
        double sgn = (m & 1) ? -1.0 : 1.0;
        Qre[(l + m) * d + (l + m)] = sgn * r2i;
        Qre[(l + m) * d + (l - m)] = r2i;
        Qim[(l - m) * d + (l - m)] = r2i;
        Qim[(l - m) * d + (l + m)] = -sgn * r2i;
    }
}

__global__ void cg_init_kernel() {
    int p = threadIdx.x;
    if (p >= 15) return;
    int l1 = c_pl1[p], l2 = c_pl2[p], l3 = c_pl3[p];
    int d1 = 2 * l1 + 1, d2 = 2 * l2 + 1, d3 = 2 * l3 + 1;

    double Q1r[25], Q1i[25], Q2r[25], Q2i[25], Q3r[25], Q3i[25];
    buildQ(l1, Q1r, Q1i); buildQ(l2, Q2r, Q2i); buildQ(l3, Q3r, Q3i);

    double Mr[5][5][5], Mi[5][5][5];
    double maxr = 0.0, maxi = 0.0;
    for (int i = 0; i < d1; ++i)
    for (int j = 0; j < d2; ++j)
    for (int k = 0; k < d3; ++k) {
        double sr = 0.0, si = 0.0;
        for (int a = 0; a < d1; ++a) {
            double q1r = Q1r[i * d1 + a], q1i = -Q1i[i * d1 + a];  // conj
            if (q1r == 0.0 && q1i == 0.0) continue;
            for (int b = 0; b < d2; ++b) {
                double q2r = Q2r[j * d2 + b], q2i = -Q2i[j * d2 + b];  // conj
                if (q2r == 0.0 && q2i == 0.0) continue;
                int m1 = a - l1, m2 = b - l2, m3 = m1 + m2;
                if (m3 < -l3 || m3 > l3) continue;
                double C = cgc(l1, m1, l2, m2, l3, m3);
                if (C == 0.0) continue;
                int c = m3 + l3;
                double q3r = Q3r[k * d3 + c], q3i = Q3i[k * d3 + c];
                double q12r = q1r * q2r - q1i * q2i;
                double q12i = q1r * q2i + q1i * q2r;
                sr += (q12r * q3r - q12i * q3i) * C;
                si += (q12r * q3i + q12i * q3r) * C;
            }
        }
        Mr[i][j][k] = sr; Mi[i][j][k] = si;
        maxr = fmax(maxr, fabs(sr));
        maxi = fmax(maxi, fabs(si));
    }
    bool flip = (maxi > maxr);   // reference multiplies by -1j; real part becomes Mi
    for (int k = 0; k < d3; ++k) {
        int cnt = 0;
        for (int i = 0; i < d1; ++i)
        for (int j = 0; j < d2; ++j) {
            double val = flip ? Mi[i][j][k] : Mr[i][j][k];
            if (fabs(val) > 1e-8) {
                g_cgij[p][k][cnt] = (i << 3) | j;
                g_cgval[p][k][cnt] = (float)val;
                ++cnt;
            }
        }
        g_cgcnt[p][k] = cnt;
    }
    // zero unused k slots
    for (int k = d3; k < 5; ++k) g_cgcnt[p][k] = 0;
}

// ============================================================================
// Kernel 1: branch linears  a = (x @ W1)/8,  b = (x @ W2)/8  -> g_A, g_B
// one warp per row n
// ============================================================================

__global__ __launch_bounds__(256) void ab_kernel(
    const float* __restrict__ x0, const float* __restrict__ x1, const float* __restrict__ x2,
    const float* __restrict__ W10, const float* __restrict__ W11, const float* __restrict__ W12,
    const float* __restrict__ W20, const float* __restrict__ W21, const float* __restrict__ W22,
    int Nrows)
{
    __shared__ float sx[8][576];
    const int lane = threadIdx.x & 31;
    const int wid = threadIdx.x >> 5;
    const int n = blockIdx.x * 8 + wid;
    if (n >= Nrows) return;

    for (int t = lane; t < 64;  t += 32) sx[wid][t]       = x0[(size_t)n * 64  + t];
    for (int t = lane; t < 192; t += 32) sx[wid][64 + t]  = x1[(size_t)n * 192 + t];
    for (int t = lane; t < 320; t += 32) sx[wid][256 + t] = x2[(size_t)n * 320 + t];
    __syncwarp();

    const float* W1s[3] = {W10, W11, W12};
    const float* W2s[3] = {W20, W21, W22};

    #pragma unroll 1
    for (int o = lane; o < 288; o += 32) {
        const int branch = (o >= 144);
        const int ol = o - branch * 144;
        int l, v, i, xo, d;
        if (ol < 16)      { l = 0; v = ol;            i = 0;          xo = 0;   d = 1; }
        else if (ol < 64) { l = 1; int t = ol - 16;   v = t / 3; i = t - 3 * v; xo = 64;  d = 3; }
        else              { l = 2; int t = ol - 64;   v = t / 5; i = t - 5 * v; xo = 256; d = 5; }
        const float* W = branch ? W2s[l] : W1s[l];
        float acc = 0.f;
        #pragma unroll 8
        for (int u = 0; u < 64; ++u)
            acc = fmaf(sx[wid][xo + u * d + i], W[u * 16 + v], acc);
        (branch ? g_B : g_A)[(size_t)n * 144 + ol] = acc * 0.125f;
    }
}

// ============================================================================
// Kernel 2 (x3): fused CG tensor product + W3 GEMM for one output degree LOUT.
//   CTA: 256 threads, M=32 rows. smem: A,B rows + z-chunk [NK][32][64].
//   GEMM: warp wid owns rows wid*4..+3; thread owns w = {lane, lane+32};
//   accumulators acc[4 rows][2 w][NK].
// ============================================================================

template<int LOUT, int NP>
__global__ __launch_bounds__(256, 2) void tp_kernel(
    const float* __restrict__ W3, float* __restrict__ out, int Nrows)
{
    constexpr int NK = 2 * LOUT + 1;
    constexpr int M = 32;
    constexpr int OOFF = (LOUT == 0) ? 0 : ((LOUT == 1) ? 64 : 256);

    extern __shared__ float sm[];
    float* sA = sm;                 // [M][144]
    float* sB = sm + M * 144;       // [M][144]
    float* sZ = sm + 2 * M * 144;   // [NK][M][64]

    const int tid  = threadIdx.x;
    const int lane = tid & 31;
    const int wid  = tid >> 5;
    const int n0   = blockIdx.x * M;

    // ---- load A,B rows ----
    for (int idx = tid; idx < M * 144; idx += 256) {
        const int r = idx / 144;
        const int c = idx - r * 144;
        if (n0 + r < Nrows) {
            sA[idx] = g_A[(size_t)(n0 + r) * 144 + c];
            sB[idx] = g_B[(size_t)(n0 + r) * 144 + c];
        } else {
            sA[idx] = 0.f; sB[idx] = 0.f;
        }
    }

    float acc[4][2][NK];
    #pragma unroll
    for (int r = 0; r < 4; ++r)
        #pragma unroll
        for (int h = 0; h < 2; ++h)
            #pragma unroll
            for (int k = 0; k < NK; ++k) acc[r][h][k] = 0.f;

    const int uvc = tid & 63;       // uv within chunk
    const int rb  = tid >> 6;       // 0..3 (z-compute row base)
    const int v   = uvc & 15;
    int rbase[8];
    #pragma unroll
    for (int s = 0; s < 8; ++s) rbase[s] = (rb + 4 * s) * 144;
    const int warp_r0 = wid * 4;    // GEMM rows for this warp

    __syncthreads();

    #pragma unroll 1
    for (int p = 0; p < NP; ++p) {
        const int pg   = c_lp[LOUT][p];
        const int l1   = c_pl1[pg], l2 = c_pl2[pg];
        const int aoff = c_aoff[l1], boff = c_aoff[l2];
        const int d1   = 2 * l1 + 1, d2 = 2 * l2 + 1;
        const float* bp0 = sB + boff + v * d2;

        #pragma unroll 1
        for (int ch = 0; ch < 4; ++ch) {
            // ---- z-compute: this thread handles (rows rb+4s, uv = ch*64+uvc) ----
            {
                const int u = ch * 4 + (uvc >> 4);
                const float* ap0 = sA + aoff + u * d1;
                #pragma unroll
                for (int k = 0; k < NK; ++k) {
                    float zk[8];
                    #pragma unroll
                    for (int s = 0; s < 8; ++s) zk[s] = 0.f;
                    const int cnt = g_cgcnt[pg][k];
                    for (int e = 0; e < cnt; ++e) {
                        const int   ij = g_cgij[pg][k][e];
                        const float c  = g_cgval[pg][k][e];
                        const int i = ij >> 3, j = ij & 7;
                        #pragma unroll
                        for (int s = 0; s < 8; ++s)
                            zk[s] = fmaf(ap0[rbase[s] + i] * bp0[rbase[s] + j], c, zk[s]);
                    }
                    #pragma unroll
                    for (int s = 0; s < 8; ++s)
                        sZ[k * (M * 64) + (rb + 4 * s) * 64 + uvc] = zk[s];
                }
            }
            __syncthreads();

            // ---- GEMM over this 64-wide K chunk ----
            const float* W3c = W3 + (size_t)(p * 256 + ch * 64) * 64;
            #pragma unroll 2
            for (int q = 0; q < 64; ++q) {
                const float w0 = W3c[q * 64 + lane];
                const float w1 = W3c[q * 64 + lane + 32];
                #pragma unroll
                for (int r = 0; r < 4; ++r) {
                    const int zb = (warp_r0 + r) * 64 + q;
                    #pragma unroll
                    for (int k = 0; k < NK; ++k) {
                        const float zv = sZ[k * (M * 64) + zb];
                        acc[r][0][k] = fmaf(w0, zv, acc[r][0][k]);
                        acc[r][1][k] = fmaf(w1, zv, acc[r][1][k]);
                    }
                }
            }
            __syncthreads();
        }
    }

    // ---- epilogue: y = acc / sqrt(tp_mult) ----
    const float scale = rsqrtf((float)(NP * 256));
    #pragma unroll
    for (int r = 0; r < 4; ++r) {
        const int n = n0 + warp_r0 + r;
        if (n >= Nrows) continue;
        float* o = out + (size_t)n * 576 + OOFF;
        #pragma unroll
        for (int k = 0; k < NK; ++k) {
            o[lane * NK + k]        = acc[r][0][k] * scale;
            o[(lane + 32) * NK + k] = acc[r][1][k] * scale;
        }
    }
}

// ============================================================================
// kernel_launch
// Input order follows the reference setup_inputs() dict insertion order:
//   x0,x1,x2, W1_0,W2_0, W1_1,W2_1, W1_2,W2_2, W3_0,W3_1,W3_2
// (W1/W2 are INTERLEAVED per degree — they are created in the same loop.)
// ============================================================================

extern "C" void kernel_launch(void* const* d_in, const int* in_sizes, int n_in,
                              void* d_out, int out_size)
{
    const float* x0  = (const float*)d_in[0];
    const float* x1  = (const float*)d_in[1];
    const float* x2  = (const float*)d_in[2];
    const float* W10 = (const float*)d_in[3];   // W1_0
    const float* W20 = (const float*)d_in[4];   // W2_0
    const float* W11 = (const float*)d_in[5];   // W1_1
    const float* W21 = (const float*)d_in[6];   // W2_1
    const float* W12 = (const float*)d_in[7];   // W1_2
    const float* W22 = (const float*)d_in[8];   // W2_2
    const float* W30 = (const float*)d_in[9];
    const float* W31 = (const float*)d_in[10];
    const float* W32 = (const float*)d_in[11];
    float* out = (float*)d_out;

    const int N = in_sizes[0] / 64;   // x0 is [N,64,1]

    const int smem0 = (2 * 32 * 144 + 1 * 32 * 64) * 4;  // 45056
    const int smem1 = (2 * 32 * 144 + 3 * 32 * 64) * 4;  // 61440
    const int smem2 = (2 * 32 * 144 + 5 * 32 * 64) * 4;  // 77824
    cudaFuncSetAttribute(tp_kernel<0, 3>, cudaFuncAttributeMaxDynamicSharedMemorySize, smem0);
    cudaFuncSetAttribute(tp_kernel<1, 6>, cudaFuncAttributeMaxDynamicSharedMemorySize, smem1);
    cudaFuncSetAttribute(tp_kernel<2, 6>, cudaFuncAttributeMaxDynamicSharedMemorySize, smem2);

    cg_init_kernel<<<1, 32>>>();
    ab_kernel<<<(N + 7) / 8, 256>>>(x0, x1, x2, W10, W11, W12, W20, W21, W22, N);

    const int nb = (N + 31) / 32;
    tp_kernel<0, 3><<<nb, 256, smem0>>>(W30, out, N);
    tp_kernel<1, 6><<<nb, 256, smem1>>>(W31, out, N);
    tp_kernel<2, 6><<<nb, 256, smem2>>>(W32, out, N);
}